// round 4
// baseline (speedup 1.0000x reference)
#include <cuda_runtime.h>
#include <cuda_bf16.h>
#include <cstdint>

#define DDIM 768
#define NQ   4096
#define KC   65536
#define BM   128
#define BN   128
#define BKB  128             // k-bytes (= k-elems, int8) per stage
#define NSTAGE (DDIM / BKB)  // 6
#define CAP  2048
#define MARGIN 2.0e-4f

#define SCALE_A 24.0f
#define SCALE_B 8323072.0f   // 127 * 65536
static constexpr float MINUS2INV = -2.0f / (24.0f * 8323072.0f);

// ---------------------------------------------------------------------------
// Device scratch (static — no allocations allowed)
// ---------------------------------------------------------------------------
__device__ float g_zsq[NQ];
__device__ float g_esq[KC];
__device__ int8_t g_Ai8[(size_t)NQ * DDIM];   // 3 MB
__device__ int8_t g_Bi8[(size_t)KC * DDIM];   // 50 MB
__device__ unsigned int g_rowmin[NQ];         // ordered-uint encoded float
__device__ int g_cnt[NQ];
__device__ int g_cand[(size_t)NQ * CAP];      // 32 MB
__device__ double g_loss;

// ---------------------------------------------------------------------------
// Helpers
// ---------------------------------------------------------------------------
__device__ __forceinline__ uint32_t smem_u32(const void* p) {
    uint32_t a;
    asm("{ .reg .u64 t; cvta.to.shared.u64 t, %1; cvt.u32.u64 %0, t; }"
        : "=r"(a) : "l"(p));
    return a;
}
#define SW128(off) ((off) ^ (((off) >> 3) & 0x70))
#define CP16(dst, src) \
    asm volatile("cp.async.cg.shared.global [%0], [%1], 16;" :: "r"(dst), "l"(src))
#define CP_COMMIT() asm volatile("cp.async.commit_group;" ::: "memory")
#define CP_WAIT(n)  asm volatile("cp.async.wait_group %0;" :: "n"(n) : "memory")

__device__ __forceinline__ void ldm_x4(uint32_t& r0, uint32_t& r1, uint32_t& r2,
                                       uint32_t& r3, uint32_t addr) {
    asm volatile("ldmatrix.sync.aligned.m8n8.x4.shared.b16 {%0,%1,%2,%3}, [%4];"
                 : "=r"(r0), "=r"(r1), "=r"(r2), "=r"(r3) : "r"(addr));
}
// int8 IMMA, exact int32 accumulate (base ISA, sm_72+)
__device__ __forceinline__ void mma_s8(int* d, const uint32_t* a,
                                       uint32_t b0, uint32_t b1) {
    asm volatile(
        "mma.sync.aligned.m16n8k32.row.col.s32.s8.s8.s32 "
        "{%0,%1,%2,%3}, {%4,%5,%6,%7}, {%8,%9}, {%0,%1,%2,%3};"
        : "+r"(d[0]), "+r"(d[1]), "+r"(d[2]), "+r"(d[3])
        : "r"(a[0]), "r"(a[1]), "r"(a[2]), "r"(a[3]), "r"(b0), "r"(b1));
}

// float <-> ordered uint (atomicMin over signed floats)
__device__ __forceinline__ unsigned fenc(float f) {
    unsigned u = __float_as_uint(f);
    return (u & 0x80000000u) ? ~u : (u | 0x80000000u);
}
__device__ __forceinline__ float fdec(unsigned u) {
    return (u & 0x80000000u) ? __uint_as_float(u & 0x7FFFFFFFu)
                             : __uint_as_float(~u);
}

// ---------------------------------------------------------------------------
// Init / norms / quantize
// ---------------------------------------------------------------------------
__global__ void init_kernel() {
    int i = blockIdx.x * blockDim.x + threadIdx.x;
    if (i < NQ) { g_rowmin[i] = 0xFFFFFFFFu; g_cnt[i] = 0; }
    if (i == 0) g_loss = 0.0;
}

// strictly-sequential fp32 norms: fl(mul) then fl(add) — validated recipe
__global__ void sqnorm_kernel(const float* __restrict__ X, float* __restrict__ out,
                              int rows) {
    int r = blockIdx.x * blockDim.x + threadIdx.x;
    if (r >= rows) return;
    const float4* x = reinterpret_cast<const float4*>(X + (size_t)r * DDIM);
    float s = 0.f;
#pragma unroll 4
    for (int i = 0; i < DDIM / 4; i++) {
        float4 v = __ldg(&x[i]);
        s = __fadd_rn(s, __fmul_rn(v.x, v.x));
        s = __fadd_rn(s, __fmul_rn(v.y, v.y));
        s = __fadd_rn(s, __fmul_rn(v.z, v.z));
        s = __fadd_rn(s, __fmul_rn(v.w, v.w));
    }
    out[r] = s;
}

__device__ __forceinline__ int8_t q8(float v, float scale) {
    int q = __float2int_rn(v * scale);
    q = q > 127 ? 127 : (q < -127 ? -127 : q);
    return (int8_t)q;
}

__global__ void quant_kernel(const float* __restrict__ X, int8_t* __restrict__ out,
                             size_t n, float scale) {
    size_t i = ((size_t)blockIdx.x * blockDim.x + threadIdx.x) * 4;
    if (i >= n) return;
    float4 v = *reinterpret_cast<const float4*>(X + i);
    char4 o;
    o.x = q8(v.x, scale); o.y = q8(v.y, scale);
    o.z = q8(v.z, scale); o.w = q8(v.w, scale);
    *reinterpret_cast<char4*>(out + i) = o;
}

// ---------------------------------------------------------------------------
// Pass 1: int8 IMMA GEMM (128x128 tile, K=768) + score prune.
//   score s~ = esq[c] - 2*dotq/(SA*SB) ; collect c with s~ <= rowMin + MARGIN
// ---------------------------------------------------------------------------
__global__ void __launch_bounds__(256, 2) pass1_kernel() {
    extern __shared__ char smem[];
    const uint32_t sb = smem_u32(smem);
    const uint32_t A_S[2] = {sb, sb + 16384};
    const uint32_t B_S[2] = {sb + 32768, sb + 49152};

    const int tid = threadIdx.x;
    const int wid = tid >> 5;
    const int lane = tid & 31;
    const int warp_m = wid >> 2;       // 0..1
    const int warp_n = wid & 3;        // 0..3
    const int bm = blockIdx.x * BM;
    const int bn = blockIdx.y * BN;

    int acc[4][4][4];
#pragma unroll
    for (int i = 0; i < 4; i++)
#pragma unroll
        for (int j = 0; j < 4; j++)
#pragma unroll
            for (int t = 0; t < 4; t++) acc[i][j][t] = 0;

    auto fill = [&](int stg, int s) {
#pragma unroll
        for (int i = 0; i < 4; i++) {
            int idx = tid + i * 256;          // 0..1023
            int row = idx >> 3, ch = idx & 7;
            const int8_t* srcA = g_Ai8 + (size_t)(bm + row) * DDIM + s * BKB + ch * 16;
            CP16(A_S[stg] + SW128(row * 128 + ch * 16), srcA);
            const int8_t* srcB = g_Bi8 + (size_t)(bn + row) * DDIM + s * BKB + ch * 16;
            CP16(B_S[stg] + SW128(row * 128 + ch * 16), srcB);
        }
        CP_COMMIT();
    };

    fill(0, 0);
    fill(1, 1);

    // per-lane ldmatrix rows (16-byte chunk addressing identical to bf16 path)
    const int a_r = warp_m * 64 + (lane & 7) + ((lane & 8) ? 8 : 0);  // + mi*16
    const int b_r = warp_n * 32 + (lane & 7) + ((lane & 8) ? 8 : 0);  // + bj*16
    const int chk = (lane >> 4) & 1;                                   // k-chunk half

    for (int s = 0; s < NSTAGE; s++) {
        if (s < NSTAGE - 1) { CP_WAIT(1); } else { CP_WAIT(0); }
        __syncthreads();
        const uint32_t Ab = A_S[s & 1], Bb = B_S[s & 1];
#pragma unroll
        for (int kk = 0; kk < 4; kk++) {            // 4 x k32 per 128B row
            const int ch = chk + kk * 2;
            uint32_t a[4][4];
#pragma unroll
            for (int mi = 0; mi < 4; mi++) {
                int r = a_r + mi * 16;
                ldm_x4(a[mi][0], a[mi][1], a[mi][2], a[mi][3],
                       Ab + (uint32_t)(r * 128 + ((ch * 16) ^ ((r & 7) << 4))));
            }
            uint32_t bf[2][4];
#pragma unroll
            for (int bj = 0; bj < 2; bj++) {
                int r = b_r + bj * 16;
                ldm_x4(bf[bj][0], bf[bj][1], bf[bj][2], bf[bj][3],
                       Bb + (uint32_t)(r * 128 + ((ch * 16) ^ ((r & 7) << 4))));
            }
#pragma unroll
            for (int mi = 0; mi < 4; mi++)
#pragma unroll
                for (int nj = 0; nj < 4; nj++)
                    mma_s8(acc[mi][nj], a[mi], bf[nj >> 1][nj & 1],
                           bf[nj >> 1][2 + (nj & 1)]);
        }
        __syncthreads();
        if (s + 2 < NSTAGE) fill(s & 1, s + 2);
    }

    // ---- epilogue: scores, running row-min, candidate collection ----
#pragma unroll
    for (int mi = 0; mi < 4; mi++) {
#pragma unroll
        for (int half = 0; half < 2; half++) {
            const int row = bm + warp_m * 64 + mi * 16 + (lane >> 2) + half * 8;
            float rmin = 3.4e38f;
            float sc[4][2];
#pragma unroll
            for (int nj = 0; nj < 4; nj++)
#pragma unroll
                for (int t = 0; t < 2; t++) {
                    int c = bn + warp_n * 32 + nj * 8 + (lane & 3) * 2 + t;
                    // (float)acc exact: |acc| <= 768*127^2 < 2^24
                    float v = __fmaf_rn(MINUS2INV,
                                        __int2float_rn(acc[mi][nj][half * 2 + t]),
                                        g_esq[c]);
                    sc[nj][t] = v;
                    rmin = fminf(rmin, v);
                }
            rmin = fminf(rmin, __shfl_xor_sync(0xFFFFFFFFu, rmin, 1));
            rmin = fminf(rmin, __shfl_xor_sync(0xFFFFFFFFu, rmin, 2));
            unsigned enc = fenc(rmin);
            unsigned old = 0xFFFFFFFFu;
            if ((lane & 3) == 0) old = atomicMin(&g_rowmin[row], enc);
            old = __shfl_sync(0xFFFFFFFFu, old, lane & ~3);
            float T = fdec(old < enc ? old : enc) + MARGIN;
#pragma unroll
            for (int nj = 0; nj < 4; nj++)
#pragma unroll
                for (int t = 0; t < 2; t++) {
                    if (sc[nj][t] <= T) {
                        int c = bn + warp_n * 32 + nj * 8 + (lane & 3) * 2 + t;
                        int pos = atomicAdd(&g_cnt[row], 1);
                        if (pos < CAP) g_cand[(size_t)row * CAP + pos] = c;
                    }
                }
        }
    }
}

// ---------------------------------------------------------------------------
// Pass 2: exact re-rank of candidates (bit-identical round-1 recipe),
// then codes / STE / loss. One block per row.
// ---------------------------------------------------------------------------
__global__ void finalize_kernel(const float* __restrict__ A,
                                const float* __restrict__ B,
                                float* __restrict__ out_codes,
                                float* __restrict__ out_q) {
    __shared__ unsigned long long sKey;
    const int n = blockIdx.x;
    if (threadIdx.x == 0) sKey = ~0ULL;
    __syncthreads();

    const float zq = g_zsq[n];
    const float* z = A + (size_t)n * DDIM;
    int cnt = g_cnt[n];
    if (cnt > CAP) cnt = CAP;

    unsigned long long best = ~0ULL;
    for (int i = threadIdx.x; i < cnt; i += blockDim.x) {
        int c = g_cand[(size_t)n * CAP + i];
        const float4* e4 = reinterpret_cast<const float4*>(B + (size_t)c * DDIM);
        const float4* z4 = reinterpret_cast<const float4*>(z);
        float dot = 0.f;
#pragma unroll 4
        for (int k = 0; k < DDIM / 4; k++) {
            float4 ev = __ldg(&e4[k]);
            float4 zv = __ldg(&z4[k]);
            dot = __fmaf_rn(zv.x, ev.x, dot);
            dot = __fmaf_rn(zv.y, ev.y, dot);
            dot = __fmaf_rn(zv.z, ev.z, dot);
            dot = __fmaf_rn(zv.w, ev.w, dot);
        }
        float anchor = __fadd_rn(zq, g_esq[c]);               // fl(z2 + e2)
        float dist = __fsub_rn(anchor, __fadd_rn(dot, dot));  // fl(a - 2*dot)
        unsigned long long key =
            ((unsigned long long)__float_as_uint(dist) << 32) |
            (unsigned long long)(unsigned)c;
        best = key < best ? key : best;
    }
    atomicMin(&sKey, best);
    __syncthreads();

    const int code = (int)(sKey & 0xFFFFFFFFULL);
    if (threadIdx.x == 0) out_codes[n] = (float)code;

    const float* q = B + (size_t)code * DDIM;
    float ls = 0.f;
    for (int i = threadIdx.x; i < DDIM; i += blockDim.x) {
        float qv = q[i];
        float zv = z[i];
        out_q[(size_t)n * DDIM + i] = __fadd_rn(zv, __fsub_rn(qv, zv));
        float d = zv - qv;
        ls = __fmaf_rn(d, d, ls);
    }
#pragma unroll
    for (int o = 16; o > 0; o >>= 1) ls += __shfl_xor_sync(0xFFFFFFFFu, ls, o);
    __shared__ float wsum[8];
    int w = threadIdx.x >> 5;
    if ((threadIdx.x & 31) == 0) wsum[w] = ls;
    __syncthreads();
    if (threadIdx.x == 0) {
        float s = 0.f;
        for (int k = 0; k < (int)(blockDim.x >> 5); k++) s += wsum[k];
        atomicAdd(&g_loss, (double)s);
    }
}

__global__ void loss_kernel(float* __restrict__ out_loss, double inv_nd) {
    if (threadIdx.x == 0) out_loss[0] = (float)(g_loss * inv_nd * 1.25);
}

// ---------------------------------------------------------------------------
extern "C" void kernel_launch(void* const* d_in, const int* in_sizes, int n_in,
                              void* d_out, int out_size) {
    const float* A = (const float*)d_in[0];  // embeddings (4096 x 768)
    const float* B = (const float*)d_in[1];  // codebook  (65536 x 768)
    const int N = in_sizes[0] / DDIM;
    const int K = in_sizes[1] / DDIM;

    float* out = (float*)d_out;
    float* out_codes = out;
    float* out_q = out + N;
    float* out_loss = out + N + (size_t)N * DDIM;

    static const int SMEM_BYTES = 65536;
    cudaFuncSetAttribute(pass1_kernel, cudaFuncAttributeMaxDynamicSharedMemorySize,
                         SMEM_BYTES);

    init_kernel<<<(NQ + 255) / 256, 256>>>();

    float* zsq_p; cudaGetSymbolAddress((void**)&zsq_p, g_zsq);
    float* esq_p; cudaGetSymbolAddress((void**)&esq_p, g_esq);
    sqnorm_kernel<<<(N + 127) / 128, 128>>>(A, zsq_p, N);
    sqnorm_kernel<<<(K + 127) / 128, 128>>>(B, esq_p, K);

    int8_t* Ai8_p; cudaGetSymbolAddress((void**)&Ai8_p, g_Ai8);
    int8_t* Bi8_p; cudaGetSymbolAddress((void**)&Bi8_p, g_Bi8);
    {
        size_t na = (size_t)N * DDIM;
        quant_kernel<<<(unsigned)((na / 4 + 255) / 256), 256>>>(A, Ai8_p, na, SCALE_A);
        size_t nb = (size_t)K * DDIM;
        quant_kernel<<<(unsigned)((nb / 4 + 255) / 256), 256>>>(B, Bi8_p, nb, SCALE_B);
    }

    dim3 grid(N / BM, K / BN);   // (32, 512) — m fastest for B-strip L2 reuse
    pass1_kernel<<<grid, 256, SMEM_BYTES>>>();

    finalize_kernel<<<N, 256>>>(A, B, out_codes, out_q);
    loss_kernel<<<1, 32>>>(out_loss, 1.0 / ((double)N * (double)DDIM));
}

// round 5
// speedup vs baseline: 2.2387x; 2.2387x over previous
#include <cuda_runtime.h>
#include <cuda_fp16.h>
#include <cstdint>

#define DDIM 768
#define NQ   4096
#define KC   65536
#define BM   128
#define BN   128
#define BK   64              // k elems per stage (128B fp16 rows)
#define NSTAGE (DDIM / BK)   // 12
#define CAP  2048
#define MARGIN 2.0e-4f

// B stored as e * 65536 in fp16; dot' = dot * 65536
static constexpr float MINUS2INV = -2.0f / 65536.0f;

// ---------------------------------------------------------------------------
// Device scratch (static — no allocations allowed)
// ---------------------------------------------------------------------------
__device__ float g_zsq[NQ];
__device__ float g_esq[KC];
__device__ __half g_Ah[(size_t)NQ * DDIM];    // 6 MB
__device__ __half g_Bh[(size_t)KC * DDIM];    // 100 MB
__device__ unsigned int g_rowmin[NQ];         // ordered-uint encoded float
__device__ int g_cnt[NQ];
__device__ int g_cand[(size_t)NQ * CAP];      // 32 MB
__device__ double g_loss;

// ---------------------------------------------------------------------------
// Helpers
// ---------------------------------------------------------------------------
__device__ __forceinline__ uint32_t smem_u32(const void* p) {
    uint32_t a;
    asm("{ .reg .u64 t; cvta.to.shared.u64 t, %1; cvt.u32.u64 %0, t; }"
        : "=r"(a) : "l"(p));
    return a;
}
#define SW128(off) ((off) ^ (((off) >> 3) & 0x70))
#define CP16(dst, src) \
    asm volatile("cp.async.cg.shared.global [%0], [%1], 16;" :: "r"(dst), "l"(src))
#define CP_COMMIT() asm volatile("cp.async.commit_group;" ::: "memory")
#define CP_WAIT(n)  asm volatile("cp.async.wait_group %0;" :: "n"(n) : "memory")

__device__ __forceinline__ void ldm_x4(uint32_t& r0, uint32_t& r1, uint32_t& r2,
                                       uint32_t& r3, uint32_t addr) {
    asm volatile("ldmatrix.sync.aligned.m8n8.x4.shared.b16 {%0,%1,%2,%3}, [%4];"
                 : "=r"(r0), "=r"(r1), "=r"(r2), "=r"(r3) : "r"(addr));
}
// fp16 HMMA with fp16 accumulators (2 packed half2 regs)
__device__ __forceinline__ void mma_f16acc(uint32_t* d, const uint32_t* a,
                                           uint32_t b0, uint32_t b1) {
    asm volatile(
        "mma.sync.aligned.m16n8k16.row.col.f16.f16.f16.f16 "
        "{%0,%1}, {%2,%3,%4,%5}, {%6,%7}, {%0,%1};"
        : "+r"(d[0]), "+r"(d[1])
        : "r"(a[0]), "r"(a[1]), "r"(a[2]), "r"(a[3]), "r"(b0), "r"(b1));
}

// float <-> ordered uint (atomicMin over signed floats)
__device__ __forceinline__ unsigned fenc(float f) {
    unsigned u = __float_as_uint(f);
    return (u & 0x80000000u) ? ~u : (u | 0x80000000u);
}
__device__ __forceinline__ float fdec(unsigned u) {
    return (u & 0x80000000u) ? __uint_as_float(u & 0x7FFFFFFFu)
                             : __uint_as_float(~u);
}

// ---------------------------------------------------------------------------
// Init / norms / convert
// ---------------------------------------------------------------------------
__global__ void init_kernel() {
    int i = blockIdx.x * blockDim.x + threadIdx.x;
    if (i < NQ) { g_rowmin[i] = 0xFFFFFFFFu; g_cnt[i] = 0; }
    if (i == 0) g_loss = 0.0;
}

// strictly-sequential fp32 norms: fl(mul) then fl(add) — validated recipe
__global__ void sqnorm_kernel(const float* __restrict__ X, float* __restrict__ out,
                              int rows) {
    int r = blockIdx.x * blockDim.x + threadIdx.x;
    if (r >= rows) return;
    const float4* x = reinterpret_cast<const float4*>(X + (size_t)r * DDIM);
    float s = 0.f;
#pragma unroll 4
    for (int i = 0; i < DDIM / 4; i++) {
        float4 v = __ldg(&x[i]);
        s = __fadd_rn(s, __fmul_rn(v.x, v.x));
        s = __fadd_rn(s, __fmul_rn(v.y, v.y));
        s = __fadd_rn(s, __fmul_rn(v.z, v.z));
        s = __fadd_rn(s, __fmul_rn(v.w, v.w));
    }
    out[r] = s;
}

__global__ void convert_kernel(const float* __restrict__ X, __half* __restrict__ out,
                               size_t n, float scale) {
    size_t i = ((size_t)blockIdx.x * blockDim.x + threadIdx.x) * 4;
    if (i >= n) return;
    float4 v = *reinterpret_cast<const float4*>(X + i);
    __half2* o = reinterpret_cast<__half2*>(out + i);
    o[0] = __floats2half2_rn(v.x * scale, v.y * scale);
    o[1] = __floats2half2_rn(v.z * scale, v.w * scale);
}

// ---------------------------------------------------------------------------
// Pass 1: fp16 HMMA GEMM (fp16 accum), 128x128 tile, K=768 + score prune.
//   score s~ = esq[c] - 2*dot'/65536 ; collect c with s~ <= rowMin + MARGIN
// ---------------------------------------------------------------------------
__global__ void __launch_bounds__(256) pass1_kernel() {
    extern __shared__ char smem[];
    const uint32_t sb = smem_u32(smem);
    const uint32_t A_S[2] = {sb, sb + 16384};
    const uint32_t B_S[2] = {sb + 32768, sb + 49152};

    const int tid = threadIdx.x;
    const int wid = tid >> 5;
    const int lane = tid & 31;
    const int warp_m = wid >> 2;       // 0..1
    const int warp_n = wid & 3;        // 0..3
    const int bm = blockIdx.x * BM;
    const int bn = blockIdx.y * BN;

    uint32_t acc[4][4][2];             // half2-packed fp16 accumulators
#pragma unroll
    for (int i = 0; i < 4; i++)
#pragma unroll
        for (int j = 0; j < 4; j++) { acc[i][j][0] = 0u; acc[i][j][1] = 0u; }

    auto fill = [&](int stg, int s) {
#pragma unroll
        for (int i = 0; i < 4; i++) {
            int idx = tid + i * 256;          // 0..1023
            int row = idx >> 3, ch = idx & 7;
            const __half* srcA = g_Ah + (size_t)(bm + row) * DDIM + s * BK + ch * 8;
            CP16(A_S[stg] + SW128(row * 128 + ch * 16), srcA);
            const __half* srcB = g_Bh + (size_t)(bn + row) * DDIM + s * BK + ch * 8;
            CP16(B_S[stg] + SW128(row * 128 + ch * 16), srcB);
        }
        CP_COMMIT();
    };

    fill(0, 0);
    fill(1, 1);

    const int a_r = warp_m * 64 + (lane & 7) + ((lane & 8) ? 8 : 0);  // + mi*16
    const int b_r = warp_n * 32 + (lane & 7) + ((lane & 8) ? 8 : 0);  // + bj*16
    const int chk = (lane >> 4) & 1;

    for (int s = 0; s < NSTAGE; s++) {
        if (s < NSTAGE - 1) { CP_WAIT(1); } else { CP_WAIT(0); }
        __syncthreads();
        const uint32_t Ab = A_S[s & 1], Bb = B_S[s & 1];
#pragma unroll
        for (int kk = 0; kk < 4; kk++) {
            const int ch = chk + kk * 2;
            uint32_t a[4][4];
#pragma unroll
            for (int mi = 0; mi < 4; mi++) {
                int r = a_r + mi * 16;
                ldm_x4(a[mi][0], a[mi][1], a[mi][2], a[mi][3],
                       Ab + (uint32_t)(r * 128 + ((ch * 16) ^ ((r & 7) << 4))));
            }
            uint32_t bf[2][4];
#pragma unroll
            for (int bj = 0; bj < 2; bj++) {
                int r = b_r + bj * 16;
                ldm_x4(bf[bj][0], bf[bj][1], bf[bj][2], bf[bj][3],
                       Bb + (uint32_t)(r * 128 + ((ch * 16) ^ ((r & 7) << 4))));
            }
#pragma unroll
            for (int mi = 0; mi < 4; mi++)
#pragma unroll
                for (int nj = 0; nj < 4; nj++)
                    mma_f16acc(acc[mi][nj], a[mi], bf[nj >> 1][nj & 1],
                               bf[nj >> 1][2 + (nj & 1)]);
        }
        __syncthreads();
        if (s + 2 < NSTAGE) fill(s & 1, s + 2);
    }

    // ---- epilogue: scores, running row-min, candidate collection ----
#pragma unroll
    for (int mi = 0; mi < 4; mi++) {
#pragma unroll
        for (int half = 0; half < 2; half++) {
            const int row = bm + warp_m * 64 + mi * 16 + (lane >> 2) + half * 8;
            float rmin = 3.4e38f;
            float sc[4][2];
#pragma unroll
            for (int nj = 0; nj < 4; nj++) {
                float2 d2 = __half22float2(
                    *reinterpret_cast<__half2*>(&acc[mi][nj][half]));
#pragma unroll
                for (int t = 0; t < 2; t++) {
                    int c = bn + warp_n * 32 + nj * 8 + (lane & 3) * 2 + t;
                    float dotp = t == 0 ? d2.x : d2.y;
                    float v = __fmaf_rn(MINUS2INV, dotp, g_esq[c]);
                    sc[nj][t] = v;
                    rmin = fminf(rmin, v);
                }
            }
            rmin = fminf(rmin, __shfl_xor_sync(0xFFFFFFFFu, rmin, 1));
            rmin = fminf(rmin, __shfl_xor_sync(0xFFFFFFFFu, rmin, 2));
            unsigned enc = fenc(rmin);
            unsigned old = 0xFFFFFFFFu;
            if ((lane & 3) == 0) old = atomicMin(&g_rowmin[row], enc);
            old = __shfl_sync(0xFFFFFFFFu, old, lane & ~3);
            float T = fdec(old < enc ? old : enc) + MARGIN;
#pragma unroll
            for (int nj = 0; nj < 4; nj++)
#pragma unroll
                for (int t = 0; t < 2; t++) {
                    if (sc[nj][t] <= T) {
                        int c = bn + warp_n * 32 + nj * 8 + (lane & 3) * 2 + t;
                        int pos = atomicAdd(&g_cnt[row], 1);
                        if (pos < CAP) g_cand[(size_t)row * CAP + pos] = c;
                    }
                }
        }
    }
}

// ---------------------------------------------------------------------------
// Pass 2: exact re-rank of candidates (bit-identical round-1 recipe),
// then codes / STE / loss. One block per row.
// ---------------------------------------------------------------------------
__global__ void finalize_kernel(const float* __restrict__ A,
                                const float* __restrict__ B,
                                float* __restrict__ out_codes,
                                float* __restrict__ out_q) {
    __shared__ unsigned long long sKey;
    const int n = blockIdx.x;
    if (threadIdx.x == 0) sKey = ~0ULL;
    __syncthreads();

    const float zq = g_zsq[n];
    const float* z = A + (size_t)n * DDIM;
    int cnt = g_cnt[n];
    if (cnt > CAP) cnt = CAP;

    unsigned long long best = ~0ULL;
    for (int i = threadIdx.x; i < cnt; i += blockDim.x) {
        int c = g_cand[(size_t)n * CAP + i];
        const float4* e4 = reinterpret_cast<const float4*>(B + (size_t)c * DDIM);
        const float4* z4 = reinterpret_cast<const float4*>(z);
        float dot = 0.f;
#pragma unroll 4
        for (int k = 0; k < DDIM / 4; k++) {
            float4 ev = __ldg(&e4[k]);
            float4 zv = __ldg(&z4[k]);
            dot = __fmaf_rn(zv.x, ev.x, dot);
            dot = __fmaf_rn(zv.y, ev.y, dot);
            dot = __fmaf_rn(zv.z, ev.z, dot);
            dot = __fmaf_rn(zv.w, ev.w, dot);
        }
        float anchor = __fadd_rn(zq, g_esq[c]);               // fl(z2 + e2)
        float dist = __fsub_rn(anchor, __fadd_rn(dot, dot));  // fl(a - 2*dot)
        unsigned long long key =
            ((unsigned long long)__float_as_uint(dist) << 32) |
            (unsigned long long)(unsigned)c;
        best = key < best ? key : best;
    }
    atomicMin(&sKey, best);
    __syncthreads();

    const int code = (int)(sKey & 0xFFFFFFFFULL);
    if (threadIdx.x == 0) out_codes[n] = (float)code;

    const float* q = B + (size_t)code * DDIM;
    float ls = 0.f;
    for (int i = threadIdx.x; i < DDIM; i += blockDim.x) {
        float qv = q[i];
        float zv = z[i];
        out_q[(size_t)n * DDIM + i] = __fadd_rn(zv, __fsub_rn(qv, zv));
        float d = zv - qv;
        ls = __fmaf_rn(d, d, ls);
    }
#pragma unroll
    for (int o = 16; o > 0; o >>= 1) ls += __shfl_xor_sync(0xFFFFFFFFu, ls, o);
    __shared__ float wsum[8];
    int w = threadIdx.x >> 5;
    if ((threadIdx.x & 31) == 0) wsum[w] = ls;
    __syncthreads();
    if (threadIdx.x == 0) {
        float s = 0.f;
        for (int k = 0; k < (int)(blockDim.x >> 5); k++) s += wsum[k];
        atomicAdd(&g_loss, (double)s);
    }
}

__global__ void loss_kernel(float* __restrict__ out_loss, double inv_nd) {
    if (threadIdx.x == 0) out_loss[0] = (float)(g_loss * inv_nd * 1.25);
}

// ---------------------------------------------------------------------------
extern "C" void kernel_launch(void* const* d_in, const int* in_sizes, int n_in,
                              void* d_out, int out_size) {
    const float* A = (const float*)d_in[0];  // embeddings (4096 x 768)
    const float* B = (const float*)d_in[1];  // codebook  (65536 x 768)
    const int N = in_sizes[0] / DDIM;
    const int K = in_sizes[1] / DDIM;

    float* out = (float*)d_out;
    float* out_codes = out;
    float* out_q = out + N;
    float* out_loss = out + N + (size_t)N * DDIM;

    static const int SMEM_BYTES = 65536;
    cudaFuncSetAttribute(pass1_kernel, cudaFuncAttributeMaxDynamicSharedMemorySize,
                         SMEM_BYTES);

    init_kernel<<<(NQ + 255) / 256, 256>>>();

    float* zsq_p; cudaGetSymbolAddress((void**)&zsq_p, g_zsq);
    float* esq_p; cudaGetSymbolAddress((void**)&esq_p, g_esq);
    sqnorm_kernel<<<(N + 127) / 128, 128>>>(A, zsq_p, N);
    sqnorm_kernel<<<(K + 127) / 128, 128>>>(B, esq_p, K);

    __half* Ah_p; cudaGetSymbolAddress((void**)&Ah_p, g_Ah);
    __half* Bh_p; cudaGetSymbolAddress((void**)&Bh_p, g_Bh);
    {
        size_t na = (size_t)N * DDIM;
        convert_kernel<<<(unsigned)((na / 4 + 255) / 256), 256>>>(A, Ah_p, na, 1.0f);
        size_t nb = (size_t)K * DDIM;
        convert_kernel<<<(unsigned)((nb / 4 + 255) / 256), 256>>>(B, Bh_p, nb, 65536.0f);
    }

    dim3 grid(N / BM, K / BN);   // (32, 512) — m fastest for B-strip L2 reuse
    pass1_kernel<<<grid, 256, SMEM_BYTES>>>();

    finalize_kernel<<<N, 256>>>(A, B, out_codes, out_q);
    loss_kernel<<<1, 32>>>(out_loss, 1.0 / ((double)N * (double)DDIM));
}

// round 6
// speedup vs baseline: 2.2787x; 1.0179x over previous
#include <cuda_runtime.h>
#include <cuda_fp16.h>
#include <cstdint>

#define DDIM 768
#define NQ   4096
#define KC   65536
#define BM   128
#define BN   256
#define BK   64              // k elems per stage (128B fp16 rows)
#define NSTAGE (DDIM / BK)   // 12
#define CAP  2048
#define MARGIN 2.0e-4f

// B stored as e * 65536 in fp16; dot' = dot * 65536
static constexpr float MINUS2INV = -2.0f / 65536.0f;

// ---------------------------------------------------------------------------
// Device scratch (static — no allocations allowed)
// ---------------------------------------------------------------------------
__device__ float g_zsq[NQ];
__device__ float g_esq[KC];
__device__ __half g_Ah[(size_t)NQ * DDIM];    // 6 MB
__device__ __half g_Bh[(size_t)KC * DDIM];    // 100 MB
__device__ unsigned int g_rowmin[NQ];         // ordered-uint encoded float
__device__ int g_cnt[NQ];
__device__ int g_cand[(size_t)NQ * CAP];      // 32 MB
__device__ double g_loss;

// ---------------------------------------------------------------------------
// Helpers
// ---------------------------------------------------------------------------
__device__ __forceinline__ uint32_t smem_u32(const void* p) {
    uint32_t a;
    asm("{ .reg .u64 t; cvta.to.shared.u64 t, %1; cvt.u32.u64 %0, t; }"
        : "=r"(a) : "l"(p));
    return a;
}
#define SW128(off) ((off) ^ (((off) >> 3) & 0x70))
#define CP16(dst, src) \
    asm volatile("cp.async.cg.shared.global [%0], [%1], 16;" :: "r"(dst), "l"(src))
#define CP_COMMIT() asm volatile("cp.async.commit_group;" ::: "memory")
#define CP_WAIT(n)  asm volatile("cp.async.wait_group %0;" :: "n"(n) : "memory")

__device__ __forceinline__ void ldm_x4(uint32_t& r0, uint32_t& r1, uint32_t& r2,
                                       uint32_t& r3, uint32_t addr) {
    asm volatile("ldmatrix.sync.aligned.m8n8.x4.shared.b16 {%0,%1,%2,%3}, [%4];"
                 : "=r"(r0), "=r"(r1), "=r"(r2), "=r"(r3) : "r"(addr));
}
// fp16 HMMA with fp16 accumulators (2 packed half2 regs)
__device__ __forceinline__ void mma_f16acc(uint32_t* d, const uint32_t* a,
                                           uint32_t b0, uint32_t b1) {
    asm volatile(
        "mma.sync.aligned.m16n8k16.row.col.f16.f16.f16.f16 "
        "{%0,%1}, {%2,%3,%4,%5}, {%6,%7}, {%0,%1};"
        : "+r"(d[0]), "+r"(d[1])
        : "r"(a[0]), "r"(a[1]), "r"(a[2]), "r"(a[3]), "r"(b0), "r"(b1));
}

// float <-> ordered uint (atomicMin over signed floats)
__device__ __forceinline__ unsigned fenc(float f) {
    unsigned u = __float_as_uint(f);
    return (u & 0x80000000u) ? ~u : (u | 0x80000000u);
}
__device__ __forceinline__ float fdec(unsigned u) {
    return (u & 0x80000000u) ? __uint_as_float(u & 0x7FFFFFFFu)
                             : __uint_as_float(~u);
}

// ---------------------------------------------------------------------------
// Init / norms / convert
// ---------------------------------------------------------------------------
__global__ void init_kernel() {
    int i = blockIdx.x * blockDim.x + threadIdx.x;
    if (i < NQ) { g_rowmin[i] = 0xFFFFFFFFu; g_cnt[i] = 0; }
    if (i == 0) g_loss = 0.0;
}

// strictly-sequential fp32 norms: fl(mul) then fl(add) — validated recipe
__global__ void sqnorm_kernel(const float* __restrict__ X, float* __restrict__ out,
                              int rows) {
    int r = blockIdx.x * blockDim.x + threadIdx.x;
    if (r >= rows) return;
    const float4* x = reinterpret_cast<const float4*>(X + (size_t)r * DDIM);
    float s = 0.f;
#pragma unroll 4
    for (int i = 0; i < DDIM / 4; i++) {
        float4 v = __ldg(&x[i]);
        s = __fadd_rn(s, __fmul_rn(v.x, v.x));
        s = __fadd_rn(s, __fmul_rn(v.y, v.y));
        s = __fadd_rn(s, __fmul_rn(v.z, v.z));
        s = __fadd_rn(s, __fmul_rn(v.w, v.w));
    }
    out[r] = s;
}

__global__ void convert_kernel(const float* __restrict__ X, __half* __restrict__ out,
                               size_t n, float scale) {
    size_t i = ((size_t)blockIdx.x * blockDim.x + threadIdx.x) * 4;
    if (i >= n) return;
    float4 v = *reinterpret_cast<const float4*>(X + i);
    __half2* o = reinterpret_cast<__half2*>(out + i);
    o[0] = __floats2half2_rn(v.x * scale, v.y * scale);
    o[1] = __floats2half2_rn(v.z * scale, v.w * scale);
}

// ---------------------------------------------------------------------------
// Pass 1: fp16 HMMA GEMM (fp16 accum), 128x256 tile, K=768 + score prune.
// 8 warps in 2x4; each warp computes 64x64. score s~ = esq[c] - 2*dot'/65536.
// ---------------------------------------------------------------------------
__global__ void __launch_bounds__(256, 2) pass1_kernel() {
    extern __shared__ char smem[];
    const uint32_t sb = smem_u32(smem);
    const uint32_t A_S[2] = {sb, sb + 16384};               // 128 rows x 128B
    const uint32_t B_S[2] = {sb + 32768, sb + 32768 + 32768}; // 256 rows x 128B

    const int tid = threadIdx.x;
    const int wid = tid >> 5;
    const int lane = tid & 31;
    const int warp_m = wid >> 2;       // 0..1  (64 rows each)
    const int warp_n = wid & 3;        // 0..3  (64 cols each)
    const int bm = blockIdx.x * BM;
    const int bn = blockIdx.y * BN;

    uint32_t acc[4][8][2];             // half2-packed fp16 accumulators
#pragma unroll
    for (int i = 0; i < 4; i++)
#pragma unroll
        for (int j = 0; j < 8; j++) { acc[i][j][0] = 0u; acc[i][j][1] = 0u; }

    auto fill = [&](int stg, int s) {
        // A tile: 1024 16B chunks
#pragma unroll
        for (int i = 0; i < 4; i++) {
            int idx = tid + i * 256;
            int row = idx >> 3, ch = idx & 7;
            const __half* srcA = g_Ah + (size_t)(bm + row) * DDIM + s * BK + ch * 8;
            CP16(A_S[stg] + SW128(row * 128 + ch * 16), srcA);
        }
        // B tile: 2048 16B chunks
#pragma unroll
        for (int i = 0; i < 8; i++) {
            int idx = tid + i * 256;
            int row = idx >> 3, ch = idx & 7;
            const __half* srcB = g_Bh + (size_t)(bn + row) * DDIM + s * BK + ch * 8;
            CP16(B_S[stg] + SW128(row * 128 + ch * 16), srcB);
        }
        CP_COMMIT();
    };

    fill(0, 0);
    fill(1, 1);

    const int a_r = warp_m * 64 + (lane & 7) + ((lane & 8) ? 8 : 0);  // + mi*16
    const int b_r = warp_n * 64 + (lane & 7) + ((lane & 8) ? 8 : 0);  // + bj*16
    const int chk = (lane >> 4) & 1;

    for (int s = 0; s < NSTAGE; s++) {
        if (s < NSTAGE - 1) { CP_WAIT(1); } else { CP_WAIT(0); }
        __syncthreads();
        const uint32_t Ab = A_S[s & 1], Bb = B_S[s & 1];
#pragma unroll
        for (int kk = 0; kk < 4; kk++) {
            const int ch = chk + kk * 2;
            uint32_t a[4][4];
#pragma unroll
            for (int mi = 0; mi < 4; mi++) {
                int r = a_r + mi * 16;
                ldm_x4(a[mi][0], a[mi][1], a[mi][2], a[mi][3],
                       Ab + (uint32_t)(r * 128 + ((ch * 16) ^ ((r & 7) << 4))));
            }
            uint32_t bf[4][4];
#pragma unroll
            for (int bj = 0; bj < 4; bj++) {
                int r = b_r + bj * 16;
                ldm_x4(bf[bj][0], bf[bj][1], bf[bj][2], bf[bj][3],
                       Bb + (uint32_t)(r * 128 + ((ch * 16) ^ ((r & 7) << 4))));
            }
#pragma unroll
            for (int mi = 0; mi < 4; mi++)
#pragma unroll
                for (int nj = 0; nj < 8; nj++)
                    mma_f16acc(acc[mi][nj], a[mi], bf[nj >> 1][nj & 1],
                               bf[nj >> 1][2 + (nj & 1)]);
        }
        __syncthreads();
        if (s + 2 < NSTAGE) fill(s & 1, s + 2);
    }

    // ---- epilogue: scores, running row-min, candidate collection ----
#pragma unroll
    for (int mi = 0; mi < 4; mi++) {
#pragma unroll
        for (int half = 0; half < 2; half++) {
            const int row = bm + warp_m * 64 + mi * 16 + (lane >> 2) + half * 8;
            float rmin = 3.4e38f;
            float sc[8][2];
#pragma unroll
            for (int nj = 0; nj < 8; nj++) {
                float2 d2 = __half22float2(
                    *reinterpret_cast<__half2*>(&acc[mi][nj][half]));
#pragma unroll
                for (int t = 0; t < 2; t++) {
                    int c = bn + warp_n * 64 + nj * 8 + (lane & 3) * 2 + t;
                    float dotp = t == 0 ? d2.x : d2.y;
                    float v = __fmaf_rn(MINUS2INV, dotp, g_esq[c]);
                    sc[nj][t] = v;
                    rmin = fminf(rmin, v);
                }
            }
            rmin = fminf(rmin, __shfl_xor_sync(0xFFFFFFFFu, rmin, 1));
            rmin = fminf(rmin, __shfl_xor_sync(0xFFFFFFFFu, rmin, 2));
            unsigned enc = fenc(rmin);
            unsigned old = 0xFFFFFFFFu;
            if ((lane & 3) == 0) old = atomicMin(&g_rowmin[row], enc);
            old = __shfl_sync(0xFFFFFFFFu, old, lane & ~3);
            float T = fdec(old < enc ? old : enc) + MARGIN;
#pragma unroll
            for (int nj = 0; nj < 8; nj++)
#pragma unroll
                for (int t = 0; t < 2; t++) {
                    if (sc[nj][t] <= T) {
                        int c = bn + warp_n * 64 + nj * 8 + (lane & 3) * 2 + t;
                        int pos = atomicAdd(&g_cnt[row], 1);
                        if (pos < CAP) g_cand[(size_t)row * CAP + pos] = c;
                    }
                }
        }
    }
}

// ---------------------------------------------------------------------------
// Pass 2: exact re-rank of candidates (bit-identical round-1 recipe),
// then codes / STE / loss. One block per row.
// ---------------------------------------------------------------------------
__global__ void finalize_kernel(const float* __restrict__ A,
                                const float* __restrict__ B,
                                float* __restrict__ out_codes,
                                float* __restrict__ out_q) {
    __shared__ unsigned long long sKey;
    const int n = blockIdx.x;
    if (threadIdx.x == 0) sKey = ~0ULL;
    __syncthreads();

    const float zq = g_zsq[n];
    const float* z = A + (size_t)n * DDIM;
    int cnt = g_cnt[n];
    if (cnt > CAP) cnt = CAP;

    unsigned long long best = ~0ULL;
    for (int i = threadIdx.x; i < cnt; i += blockDim.x) {
        int c = g_cand[(size_t)n * CAP + i];
        const float4* e4 = reinterpret_cast<const float4*>(B + (size_t)c * DDIM);
        const float4* z4 = reinterpret_cast<const float4*>(z);
        float dot = 0.f;
#pragma unroll 4
        for (int k = 0; k < DDIM / 4; k++) {
            float4 ev = __ldg(&e4[k]);
            float4 zv = __ldg(&z4[k]);
            dot = __fmaf_rn(zv.x, ev.x, dot);
            dot = __fmaf_rn(zv.y, ev.y, dot);
            dot = __fmaf_rn(zv.z, ev.z, dot);
            dot = __fmaf_rn(zv.w, ev.w, dot);
        }
        float anchor = __fadd_rn(zq, g_esq[c]);               // fl(z2 + e2)
        float dist = __fsub_rn(anchor, __fadd_rn(dot, dot));  // fl(a - 2*dot)
        unsigned long long key =
            ((unsigned long long)__float_as_uint(dist) << 32) |
            (unsigned long long)(unsigned)c;
        best = key < best ? key : best;
    }
    atomicMin(&sKey, best);
    __syncthreads();

    const int code = (int)(sKey & 0xFFFFFFFFULL);
    if (threadIdx.x == 0) out_codes[n] = (float)code;

    const float* q = B + (size_t)code * DDIM;
    float ls = 0.f;
    for (int i = threadIdx.x; i < DDIM; i += blockDim.x) {
        float qv = q[i];
        float zv = z[i];
        out_q[(size_t)n * DDIM + i] = __fadd_rn(zv, __fsub_rn(qv, zv));
        float d = zv - qv;
        ls = __fmaf_rn(d, d, ls);
    }
#pragma unroll
    for (int o = 16; o > 0; o >>= 1) ls += __shfl_xor_sync(0xFFFFFFFFu, ls, o);
    __shared__ float wsum[8];
    int w = threadIdx.x >> 5;
    if ((threadIdx.x & 31) == 0) wsum[w] = ls;
    __syncthreads();
    if (threadIdx.x == 0) {
        float s = 0.f;
        for (int k = 0; k < (int)(blockDim.x >> 5); k++) s += wsum[k];
        atomicAdd(&g_loss, (double)s);
    }
}

__global__ void loss_kernel(float* __restrict__ out_loss, double inv_nd) {
    if (threadIdx.x == 0) out_loss[0] = (float)(g_loss * inv_nd * 1.25);
}

// ---------------------------------------------------------------------------
extern "C" void kernel_launch(void* const* d_in, const int* in_sizes, int n_in,
                              void* d_out, int out_size) {
    const float* A = (const float*)d_in[0];  // embeddings (4096 x 768)
    const float* B = (const float*)d_in[1];  // codebook  (65536 x 768)
    const int N = in_sizes[0] / DDIM;
    const int K = in_sizes[1] / DDIM;

    float* out = (float*)d_out;
    float* out_codes = out;
    float* out_q = out + N;
    float* out_loss = out + N + (size_t)N * DDIM;

    static const int SMEM_BYTES = 2 * 16384 + 2 * 32768;  // 96 KB
    cudaFuncSetAttribute(pass1_kernel, cudaFuncAttributeMaxDynamicSharedMemorySize,
                         SMEM_BYTES);

    init_kernel<<<(NQ + 255) / 256, 256>>>();

    float* zsq_p; cudaGetSymbolAddress((void**)&zsq_p, g_zsq);
    float* esq_p; cudaGetSymbolAddress((void**)&esq_p, g_esq);
    sqnorm_kernel<<<(N + 127) / 128, 128>>>(A, zsq_p, N);
    sqnorm_kernel<<<(K + 127) / 128, 128>>>(B, esq_p, K);

    __half* Ah_p; cudaGetSymbolAddress((void**)&Ah_p, g_Ah);
    __half* Bh_p; cudaGetSymbolAddress((void**)&Bh_p, g_Bh);
    {
        size_t na = (size_t)N * DDIM;
        convert_kernel<<<(unsigned)((na / 4 + 255) / 256), 256>>>(A, Ah_p, na, 1.0f);
        size_t nb = (size_t)K * DDIM;
        convert_kernel<<<(unsigned)((nb / 4 + 255) / 256), 256>>>(B, Bh_p, nb, 65536.0f);
    }

    dim3 grid(N / BM, K / BN);   // (32, 256) — m fastest for B-strip L2 reuse
    pass1_kernel<<<grid, 256, SMEM_BYTES>>>();

    finalize_kernel<<<N, 256>>>(A, B, out_codes, out_q);
    loss_kernel<<<1, 32>>>(out_loss, 1.0 / ((double)N * (double)DDIM));
}

// round 7
// speedup vs baseline: 2.4120x; 1.0585x over previous
#include <cuda_runtime.h>
#include <cuda_fp16.h>
#include <cstdint>

#define DDIM 768
#define NQ   4096
#define KC   65536
#define BM   128
#define BN   256
#define BK   64              // k elems per stage (128B fp16 rows)
#define NSTAGE (DDIM / BK)   // 12
#define CAP  2048
#define MARGIN 2.0e-4f

// B stored as e * 65536 in fp16; dot' = dot * 65536
static constexpr float MINUS2INV = -2.0f / 65536.0f;

// ---------------------------------------------------------------------------
// Device scratch (static — no allocations allowed)
// ---------------------------------------------------------------------------
__device__ float g_zsq[NQ];
__device__ float g_esq[KC];
__device__ __half g_Ah[(size_t)NQ * DDIM];    // 6 MB
__device__ __half g_Bh[(size_t)KC * DDIM];    // 100 MB
__device__ unsigned int g_rowmin[NQ];         // ordered-uint encoded float
__device__ int g_cnt[NQ];
__device__ int g_cand[(size_t)NQ * CAP];      // 32 MB
__device__ double g_loss;

// ---------------------------------------------------------------------------
// Helpers
// ---------------------------------------------------------------------------
__device__ __forceinline__ uint32_t smem_u32(const void* p) {
    uint32_t a;
    asm("{ .reg .u64 t; cvta.to.shared.u64 t, %1; cvt.u32.u64 %0, t; }"
        : "=r"(a) : "l"(p));
    return a;
}
#define SW128(off) ((off) ^ (((off) >> 3) & 0x70))
#define CP16(dst, src) \
    asm volatile("cp.async.cg.shared.global [%0], [%1], 16;" :: "r"(dst), "l"(src))
#define CP_COMMIT() asm volatile("cp.async.commit_group;" ::: "memory")
#define CP_WAIT(n)  asm volatile("cp.async.wait_group %0;" :: "n"(n) : "memory")

__device__ __forceinline__ void ldm_x4(uint32_t& r0, uint32_t& r1, uint32_t& r2,
                                       uint32_t& r3, uint32_t addr) {
    asm volatile("ldmatrix.sync.aligned.m8n8.x4.shared.b16 {%0,%1,%2,%3}, [%4];"
                 : "=r"(r0), "=r"(r1), "=r"(r2), "=r"(r3) : "r"(addr));
}
// fp16 HMMA with fp16 accumulators (2 packed half2 regs)
__device__ __forceinline__ void mma_f16acc(uint32_t* d, const uint32_t* a,
                                           uint32_t b0, uint32_t b1) {
    asm volatile(
        "mma.sync.aligned.m16n8k16.row.col.f16.f16.f16.f16 "
        "{%0,%1}, {%2,%3,%4,%5}, {%6,%7}, {%0,%1};"
        : "+r"(d[0]), "+r"(d[1])
        : "r"(a[0]), "r"(a[1]), "r"(a[2]), "r"(a[3]), "r"(b0), "r"(b1));
}

// float <-> ordered uint (atomicMin over signed floats)
__device__ __forceinline__ unsigned fenc(float f) {
    unsigned u = __float_as_uint(f);
    return (u & 0x80000000u) ? ~u : (u | 0x80000000u);
}
__device__ __forceinline__ float fdec(unsigned u) {
    return (u & 0x80000000u) ? __uint_as_float(u & 0x7FFFFFFFu)
                             : __uint_as_float(~u);
}

// ---------------------------------------------------------------------------
// Init
// ---------------------------------------------------------------------------
__global__ void init_kernel() {
    int i = blockIdx.x * blockDim.x + threadIdx.x;
    if (i < NQ) { g_rowmin[i] = 0xFFFFFFFFu; g_cnt[i] = 0; }
    if (i == 0) g_loss = 0.0;
}

// ---------------------------------------------------------------------------
// Fused prep: coalesced single read of X -> (a) fp16*scale copy,
// (b) strictly-sequential per-row squared norm (bit-exact recipe:
// chunk-ascending, k-ascending, fl(mul) then fl(add), one accumulator).
// Block = 256 threads handles 64 rows; smem tile 64x65 fp32 (conflict-free).
// ---------------------------------------------------------------------------
#define PR 64   // rows per block
#define PC 64   // cols per chunk

__global__ void __launch_bounds__(256) prep_kernel(const float* __restrict__ X,
                                                   __half* __restrict__ outh,
                                                   float* __restrict__ outn,
                                                   float scale) {
    __shared__ float tile[PR][PC + 1];
    const int r0 = blockIdx.x * PR;
    const int tid = threadIdx.x;
    float s = 0.f;

    for (int c = 0; c < DDIM; c += PC) {
#pragma unroll
        for (int i = 0; i < 4; i++) {
            int idx = tid + i * 256;          // 0..1023
            int row = idx >> 4;               // 0..63
            int c4 = idx & 15;                // 16 float4 per row-chunk
            float4 v = __ldg(reinterpret_cast<const float4*>(
                X + (size_t)(r0 + row) * DDIM + c + c4 * 4));
            tile[row][c4 * 4 + 0] = v.x;
            tile[row][c4 * 4 + 1] = v.y;
            tile[row][c4 * 4 + 2] = v.z;
            tile[row][c4 * 4 + 3] = v.w;
            __half2 h0 = __floats2half2_rn(v.x * scale, v.y * scale);
            __half2 h1 = __floats2half2_rn(v.z * scale, v.w * scale);
            uint2 pk;
            pk.x = *reinterpret_cast<unsigned*>(&h0);
            pk.y = *reinterpret_cast<unsigned*>(&h1);
            *reinterpret_cast<uint2*>(outh + (size_t)(r0 + row) * DDIM + c + c4 * 4) = pk;
        }
        __syncthreads();
        if (tid < PR) {
#pragma unroll 8
            for (int k = 0; k < PC; k++) {
                float t = tile[tid][k];
                s = __fadd_rn(s, __fmul_rn(t, t));
            }
        }
        __syncthreads();
    }
    if (tid < PR) outn[r0 + tid] = s;
}

// ---------------------------------------------------------------------------
// Pass 1: fp16 HMMA GEMM (fp16 accum), 128x256 tile, K=768 + score prune.
// 8 warps in 2x4; each warp computes 64x64. score s~ = esq[c] - 2*dot'/65536.
// ---------------------------------------------------------------------------
__global__ void __launch_bounds__(256, 2) pass1_kernel() {
    extern __shared__ char smem[];
    const uint32_t sb = smem_u32(smem);
    const uint32_t A_S[2] = {sb, sb + 16384};                 // 128 rows x 128B
    const uint32_t B_S[2] = {sb + 32768, sb + 32768 + 32768}; // 256 rows x 128B

    const int tid = threadIdx.x;
    const int wid = tid >> 5;
    const int lane = tid & 31;
    const int warp_m = wid >> 2;       // 0..1  (64 rows each)
    const int warp_n = wid & 3;        // 0..3  (64 cols each)
    const int bm = blockIdx.x * BM;
    const int bn = blockIdx.y * BN;

    uint32_t acc[4][8][2];             // half2-packed fp16 accumulators
#pragma unroll
    for (int i = 0; i < 4; i++)
#pragma unroll
        for (int j = 0; j < 8; j++) { acc[i][j][0] = 0u; acc[i][j][1] = 0u; }

    auto fill = [&](int stg, int s) {
#pragma unroll
        for (int i = 0; i < 4; i++) {
            int idx = tid + i * 256;
            int row = idx >> 3, ch = idx & 7;
            const __half* srcA = g_Ah + (size_t)(bm + row) * DDIM + s * BK + ch * 8;
            CP16(A_S[stg] + SW128(row * 128 + ch * 16), srcA);
        }
#pragma unroll
        for (int i = 0; i < 8; i++) {
            int idx = tid + i * 256;
            int row = idx >> 3, ch = idx & 7;
            const __half* srcB = g_Bh + (size_t)(bn + row) * DDIM + s * BK + ch * 8;
            CP16(B_S[stg] + SW128(row * 128 + ch * 16), srcB);
        }
        CP_COMMIT();
    };

    fill(0, 0);
    fill(1, 1);

    const int a_r = warp_m * 64 + (lane & 7) + ((lane & 8) ? 8 : 0);  // + mi*16
    const int b_r = warp_n * 64 + (lane & 7) + ((lane & 8) ? 8 : 0);  // + bj*16
    const int chk = (lane >> 4) & 1;

    for (int s = 0; s < NSTAGE; s++) {
        if (s < NSTAGE - 1) { CP_WAIT(1); } else { CP_WAIT(0); }
        __syncthreads();
        const uint32_t Ab = A_S[s & 1], Bb = B_S[s & 1];
#pragma unroll
        for (int kk = 0; kk < 4; kk++) {
            const int ch = chk + kk * 2;
            uint32_t a[4][4];
#pragma unroll
            for (int mi = 0; mi < 4; mi++) {
                int r = a_r + mi * 16;
                ldm_x4(a[mi][0], a[mi][1], a[mi][2], a[mi][3],
                       Ab + (uint32_t)(r * 128 + ((ch * 16) ^ ((r & 7) << 4))));
            }
            uint32_t bf[4][4];
#pragma unroll
            for (int bj = 0; bj < 4; bj++) {
                int r = b_r + bj * 16;
                ldm_x4(bf[bj][0], bf[bj][1], bf[bj][2], bf[bj][3],
                       Bb + (uint32_t)(r * 128 + ((ch * 16) ^ ((r & 7) << 4))));
            }
#pragma unroll
            for (int mi = 0; mi < 4; mi++)
#pragma unroll
                for (int nj = 0; nj < 8; nj++)
                    mma_f16acc(acc[mi][nj], a[mi], bf[nj >> 1][nj & 1],
                               bf[nj >> 1][2 + (nj & 1)]);
        }
        __syncthreads();
        if (s + 2 < NSTAGE) fill(s & 1, s + 2);
    }

    // ---- epilogue: scores, running row-min, candidate collection ----
#pragma unroll
    for (int mi = 0; mi < 4; mi++) {
#pragma unroll
        for (int half = 0; half < 2; half++) {
            const int row = bm + warp_m * 64 + mi * 16 + (lane >> 2) + half * 8;
            float rmin = 3.4e38f;
            float sc[8][2];
#pragma unroll
            for (int nj = 0; nj < 8; nj++) {
                float2 d2 = __half22float2(
                    *reinterpret_cast<__half2*>(&acc[mi][nj][half]));
#pragma unroll
                for (int t = 0; t < 2; t++) {
                    int c = bn + warp_n * 64 + nj * 8 + (lane & 3) * 2 + t;
                    float dotp = t == 0 ? d2.x : d2.y;
                    float v = __fmaf_rn(MINUS2INV, dotp, g_esq[c]);
                    sc[nj][t] = v;
                    rmin = fminf(rmin, v);
                }
            }
            rmin = fminf(rmin, __shfl_xor_sync(0xFFFFFFFFu, rmin, 1));
            rmin = fminf(rmin, __shfl_xor_sync(0xFFFFFFFFu, rmin, 2));
            unsigned enc = fenc(rmin);
            unsigned old = 0xFFFFFFFFu;
            if ((lane & 3) == 0) old = atomicMin(&g_rowmin[row], enc);
            old = __shfl_sync(0xFFFFFFFFu, old, lane & ~3);
            float T = fdec(old < enc ? old : enc) + MARGIN;
#pragma unroll
            for (int nj = 0; nj < 8; nj++)
#pragma unroll
                for (int t = 0; t < 2; t++) {
                    if (sc[nj][t] <= T) {
                        int c = bn + warp_n * 64 + nj * 8 + (lane & 3) * 2 + t;
                        int pos = atomicAdd(&g_cnt[row], 1);
                        if (pos < CAP) g_cand[(size_t)row * CAP + pos] = c;
                    }
                }
        }
    }
}

// ---------------------------------------------------------------------------
// Pass 2: exact re-rank of candidates (bit-identical round-1 recipe),
// then codes / STE / loss. One block per row.
// ---------------------------------------------------------------------------
__global__ void finalize_kernel(const float* __restrict__ A,
                                const float* __restrict__ B,
                                float* __restrict__ out_codes,
                                float* __restrict__ out_q) {
    __shared__ unsigned long long sKey;
    const int n = blockIdx.x;
    if (threadIdx.x == 0) sKey = ~0ULL;
    __syncthreads();

    const float zq = g_zsq[n];
    const float* z = A + (size_t)n * DDIM;
    int cnt = g_cnt[n];
    if (cnt > CAP) cnt = CAP;

    unsigned long long best = ~0ULL;
    for (int i = threadIdx.x; i < cnt; i += blockDim.x) {
        int c = g_cand[(size_t)n * CAP + i];
        const float4* e4 = reinterpret_cast<const float4*>(B + (size_t)c * DDIM);
        const float4* z4 = reinterpret_cast<const float4*>(z);
        float dot = 0.f;
#pragma unroll 4
        for (int k = 0; k < DDIM / 4; k++) {
            float4 ev = __ldg(&e4[k]);
            float4 zv = __ldg(&z4[k]);
            dot = __fmaf_rn(zv.x, ev.x, dot);
            dot = __fmaf_rn(zv.y, ev.y, dot);
            dot = __fmaf_rn(zv.z, ev.z, dot);
            dot = __fmaf_rn(zv.w, ev.w, dot);
        }
        float anchor = __fadd_rn(zq, g_esq[c]);               // fl(z2 + e2)
        float dist = __fsub_rn(anchor, __fadd_rn(dot, dot));  // fl(a - 2*dot)
        unsigned long long key =
            ((unsigned long long)__float_as_uint(dist) << 32) |
            (unsigned long long)(unsigned)c;
        best = key < best ? key : best;
    }
    atomicMin(&sKey, best);
    __syncthreads();

    const int code = (int)(sKey & 0xFFFFFFFFULL);
    if (threadIdx.x == 0) out_codes[n] = (float)code;

    const float* q = B + (size_t)code * DDIM;
    float ls = 0.f;
    for (int i = threadIdx.x; i < DDIM; i += blockDim.x) {
        float qv = q[i];
        float zv = z[i];
        out_q[(size_t)n * DDIM + i] = __fadd_rn(zv, __fsub_rn(qv, zv));
        float d = zv - qv;
        ls = __fmaf_rn(d, d, ls);
    }
#pragma unroll
    for (int o = 16; o > 0; o >>= 1) ls += __shfl_xor_sync(0xFFFFFFFFu, ls, o);
    __shared__ float wsum[8];
    int w = threadIdx.x >> 5;
    if ((threadIdx.x & 31) == 0) wsum[w] = ls;
    __syncthreads();
    if (threadIdx.x == 0) {
        float s = 0.f;
        for (int k = 0; k < (int)(blockDim.x >> 5); k++) s += wsum[k];
        atomicAdd(&g_loss, (double)s);
    }
}

__global__ void loss_kernel(float* __restrict__ out_loss, double inv_nd) {
    if (threadIdx.x == 0) out_loss[0] = (float)(g_loss * inv_nd * 1.25);
}

// ---------------------------------------------------------------------------
extern "C" void kernel_launch(void* const* d_in, const int* in_sizes, int n_in,
                              void* d_out, int out_size) {
    const float* A = (const float*)d_in[0];  // embeddings (4096 x 768)
    const float* B = (const float*)d_in[1];  // codebook  (65536 x 768)
    const int N = in_sizes[0] / DDIM;
    const int K = in_sizes[1] / DDIM;

    float* out = (float*)d_out;
    float* out_codes = out;
    float* out_q = out + N;
    float* out_loss = out + N + (size_t)N * DDIM;

    static const int SMEM_BYTES = 2 * 16384 + 2 * 32768;  // 96 KB
    cudaFuncSetAttribute(pass1_kernel, cudaFuncAttributeMaxDynamicSharedMemorySize,
                         SMEM_BYTES);

    init_kernel<<<(NQ + 255) / 256, 256>>>();

    float* zsq_p; cudaGetSymbolAddress((void**)&zsq_p, g_zsq);
    float* esq_p; cudaGetSymbolAddress((void**)&esq_p, g_esq);
    __half* Ah_p; cudaGetSymbolAddress((void**)&Ah_p, g_Ah);
    __half* Bh_p; cudaGetSymbolAddress((void**)&Bh_p, g_Bh);

    // fused coalesced prep: norm (bit-exact order) + fp16 convert, one read
    prep_kernel<<<N / PR, 256>>>(A, Ah_p, zsq_p, 1.0f);
    prep_kernel<<<K / PR, 256>>>(B, Bh_p, esq_p, 65536.0f);

    dim3 grid(N / BM, K / BN);   // (32, 256) — m fastest for B-strip L2 reuse
    pass1_kernel<<<grid, 256, SMEM_BYTES>>>();

    finalize_kernel<<<N, 256>>>(A, B, out_codes, out_q);
    loss_kernel<<<1, 32>>>(out_loss, 1.0 / ((double)N * (double)DDIM));
}

// round 9
// speedup vs baseline: 2.5659x; 1.0638x over previous
#include <cuda_runtime.h>
#include <cuda_fp16.h>
#include <cstdint>

#define DDIM 768
#define NQ   4096
#define KC   65536
#define BM   128
#define BN   256
#define BK   64              // k elems per stage (128B fp16 rows)
#define NSTAGE (DDIM / BK)   // 12
#define CAP  2048
#define MARGIN 2.0e-4f       // collection margin (vs running min)
#define FILTER 1.45e-4f      // finalize filter (vs converged min)

// B stored as e * 65536 in fp16; dot' = dot * 65536
static constexpr float MINUS2INV = -2.0f / 65536.0f;

// ---------------------------------------------------------------------------
// Device scratch (static — no allocations allowed)
// ---------------------------------------------------------------------------
__device__ float g_zsq[NQ];
__device__ float g_esq[KC];
__device__ __half g_Ah[(size_t)NQ * DDIM];    // 6 MB
__device__ __half g_Bh[(size_t)KC * DDIM];    // 100 MB
__device__ unsigned int g_rowmin[NQ];         // ordered-uint encoded float
__device__ int g_cnt[NQ];
__device__ unsigned long long g_cand[(size_t)NQ * CAP];  // (score|idx), 64 MB
__device__ double g_loss;

// ---------------------------------------------------------------------------
// Helpers
// ---------------------------------------------------------------------------
__device__ __forceinline__ uint32_t smem_u32(const void* p) {
    uint32_t a;
    asm("{ .reg .u64 t; cvta.to.shared.u64 t, %1; cvt.u32.u64 %0, t; }"
        : "=r"(a) : "l"(p));
    return a;
}
#define SW128(off) ((off) ^ (((off) >> 3) & 0x70))
#define CP16(dst, src) \
    asm volatile("cp.async.cg.shared.global [%0], [%1], 16;" :: "r"(dst), "l"(src))
#define CP_COMMIT() asm volatile("cp.async.commit_group;" ::: "memory")
#define CP_WAIT(n)  asm volatile("cp.async.wait_group %0;" :: "n"(n) : "memory")

__device__ __forceinline__ void ldm_x4(uint32_t& r0, uint32_t& r1, uint32_t& r2,
                                       uint32_t& r3, uint32_t addr) {
    asm volatile("ldmatrix.sync.aligned.m8n8.x4.shared.b16 {%0,%1,%2,%3}, [%4];"
                 : "=r"(r0), "=r"(r1), "=r"(r2), "=r"(r3) : "r"(addr));
}
// fp16 HMMA with fp16 accumulators (2 packed half2 regs)
__device__ __forceinline__ void mma_f16acc(uint32_t* d, const uint32_t* a,
                                           uint32_t b0, uint32_t b1) {
    asm volatile(
        "mma.sync.aligned.m16n8k16.row.col.f16.f16.f16.f16 "
        "{%0,%1}, {%2,%3,%4,%5}, {%6,%7}, {%0,%1};"
        : "+r"(d[0]), "+r"(d[1])
        : "r"(a[0]), "r"(a[1]), "r"(a[2]), "r"(a[3]), "r"(b0), "r"(b1));
}

// float <-> ordered uint (atomicMin over signed floats)
__device__ __forceinline__ unsigned fenc(float f) {
    unsigned u = __float_as_uint(f);
    return (u & 0x80000000u) ? ~u : (u | 0x80000000u);
}
__device__ __forceinline__ float fdec(unsigned u) {
    return (u & 0x80000000u) ? __uint_as_float(u & 0x7FFFFFFFu)
                             : __uint_as_float(~u);
}

// ---------------------------------------------------------------------------
// Init
// ---------------------------------------------------------------------------
__global__ void init_kernel() {
    int i = blockIdx.x * blockDim.x + threadIdx.x;
    if (i < NQ) { g_rowmin[i] = 0xFFFFFFFFu; g_cnt[i] = 0; }
    if (i == 0) g_loss = 0.0;
}

// ---------------------------------------------------------------------------
// Fused prep: coalesced single read of X -> (a) fp16*scale copy,
// (b) strictly-sequential per-row squared norm (bit-exact recipe).
// ---------------------------------------------------------------------------
#define PR 64   // rows per block
#define PC 64   // cols per chunk

__global__ void __launch_bounds__(256) prep_kernel(const float* __restrict__ X,
                                                   __half* __restrict__ outh,
                                                   float* __restrict__ outn,
                                                   float scale) {
    __shared__ float tile[PR][PC + 1];
    const int r0 = blockIdx.x * PR;
    const int tid = threadIdx.x;
    float s = 0.f;

    for (int c = 0; c < DDIM; c += PC) {
#pragma unroll
        for (int i = 0; i < 4; i++) {
            int idx = tid + i * 256;          // 0..1023
            int row = idx >> 4;               // 0..63
            int c4 = idx & 15;                // 16 float4 per row-chunk
            float4 v = __ldg(reinterpret_cast<const float4*>(
                X + (size_t)(r0 + row) * DDIM + c + c4 * 4));
            tile[row][c4 * 4 + 0] = v.x;
            tile[row][c4 * 4 + 1] = v.y;
            tile[row][c4 * 4 + 2] = v.z;
            tile[row][c4 * 4 + 3] = v.w;
            __half2 h0 = __floats2half2_rn(v.x * scale, v.y * scale);
            __half2 h1 = __floats2half2_rn(v.z * scale, v.w * scale);
            uint2 pk;
            pk.x = *reinterpret_cast<unsigned*>(&h0);
            pk.y = *reinterpret_cast<unsigned*>(&h1);
            *reinterpret_cast<uint2*>(outh + (size_t)(r0 + row) * DDIM + c + c4 * 4) = pk;
        }
        __syncthreads();
        if (tid < PR) {
#pragma unroll 8
            for (int k = 0; k < PC; k++) {
                float t = tile[tid][k];
                s = __fadd_rn(s, __fmul_rn(t, t));
            }
        }
        __syncthreads();
    }
    if (tid < PR) outn[r0 + tid] = s;
}

// ---------------------------------------------------------------------------
// Pass 1: fp16 HMMA GEMM (fp16 accum), 128x256 tile, K=768 + score prune.
// ---------------------------------------------------------------------------
__global__ void __launch_bounds__(256, 2) pass1_kernel() {
    extern __shared__ char smem[];
    const uint32_t sb = smem_u32(smem);
    const uint32_t A_S[2] = {sb, sb + 16384};                 // 128 rows x 128B
    const uint32_t B_S[2] = {sb + 32768, sb + 32768 + 32768}; // 256 rows x 128B

    const int tid = threadIdx.x;
    const int wid = tid >> 5;
    const int lane = tid & 31;
    const int warp_m = wid >> 2;       // 0..1  (64 rows each)
    const int warp_n = wid & 3;        // 0..3  (64 cols each)
    const int bm = blockIdx.x * BM;
    const int bn = blockIdx.y * BN;

    uint32_t acc[4][8][2];             // half2-packed fp16 accumulators
#pragma unroll
    for (int i = 0; i < 4; i++)
#pragma unroll
        for (int j = 0; j < 8; j++) { acc[i][j][0] = 0u; acc[i][j][1] = 0u; }

    // hoisted fill addressing: 32-bit byte offsets; stage advance = +128B
    const char* Abase = reinterpret_cast<const char*>(g_Ah) +
                        (uint32_t)((bm + (tid >> 3)) * (DDIM * 2) + (tid & 7) * 16);
    const char* Bbase = reinterpret_cast<const char*>(g_Bh) +
                        (uint32_t)((bn + (tid >> 3)) * (DDIM * 2) + (tid & 7) * 16);
    const uint32_t dstsw = SW128((uint32_t)((tid >> 3) * 128 + (tid & 7) * 16));

    auto fill = [&](int stg, int s) {
        const char* ap = Abase + s * 128;
        const char* bp = Bbase + s * 128;
        const uint32_t da = A_S[stg] + dstsw;
        const uint32_t db = B_S[stg] + dstsw;
#pragma unroll
        for (int i = 0; i < 4; i++)      // A: 32-row strides
            CP16(da + i * 4096, ap + i * (32 * DDIM * 2));
#pragma unroll
        for (int i = 0; i < 8; i++)      // B: 32-row strides
            CP16(db + i * 4096, bp + i * (32 * DDIM * 2));
        CP_COMMIT();
    };

    fill(0, 0);
    fill(1, 1);

    const int a_r = warp_m * 64 + (lane & 7) + ((lane & 8) ? 8 : 0);  // + mi*16
    const int b_r = warp_n * 64 + (lane & 7) + ((lane & 8) ? 8 : 0);  // + bj*16
    const int chk = (lane >> 4) & 1;

    for (int s = 0; s < NSTAGE; s++) {
        if (s < NSTAGE - 1) { CP_WAIT(1); } else { CP_WAIT(0); }
        __syncthreads();
        const uint32_t Ab = A_S[s & 1], Bb = B_S[s & 1];
#pragma unroll
        for (int kk = 0; kk < 4; kk++) {
            const int ch = chk + kk * 2;
            uint32_t a[4][4];
#pragma unroll
            for (int mi = 0; mi < 4; mi++) {
                int r = a_r + mi * 16;
                ldm_x4(a[mi][0], a[mi][1], a[mi][2], a[mi][3],
                       Ab + (uint32_t)(r * 128 + ((ch * 16) ^ ((r & 7) << 4))));
            }
            uint32_t bf[4][4];
#pragma unroll
            for (int bj = 0; bj < 4; bj++) {
                int r = b_r + bj * 16;
                ldm_x4(bf[bj][0], bf[bj][1], bf[bj][2], bf[bj][3],
                       Bb + (uint32_t)(r * 128 + ((ch * 16) ^ ((r & 7) << 4))));
            }
#pragma unroll
            for (int mi = 0; mi < 4; mi++)
#pragma unroll
                for (int nj = 0; nj < 8; nj++)
                    mma_f16acc(acc[mi][nj], a[mi], bf[nj >> 1][nj & 1],
                               bf[nj >> 1][2 + (nj & 1)]);
        }
        __syncthreads();
        if (s + 2 < NSTAGE) fill(s & 1, s + 2);
    }

    // ---- epilogue: scores, running row-min, packed candidate collection ----
#pragma unroll
    for (int mi = 0; mi < 4; mi++) {
#pragma unroll
        for (int half = 0; half < 2; half++) {
            const int row = bm + warp_m * 64 + mi * 16 + (lane >> 2) + half * 8;
            float rmin = 3.4e38f;
            float sc[8][2];
#pragma unroll
            for (int nj = 0; nj < 8; nj++) {
                float2 d2 = __half22float2(
                    *reinterpret_cast<__half2*>(&acc[mi][nj][half]));
#pragma unroll
                for (int t = 0; t < 2; t++) {
                    int c = bn + warp_n * 64 + nj * 8 + (lane & 3) * 2 + t;
                    float dotp = t == 0 ? d2.x : d2.y;
                    float v = __fmaf_rn(MINUS2INV, dotp, g_esq[c]);
                    sc[nj][t] = v;
                    rmin = fminf(rmin, v);
                }
            }
            rmin = fminf(rmin, __shfl_xor_sync(0xFFFFFFFFu, rmin, 1));
            rmin = fminf(rmin, __shfl_xor_sync(0xFFFFFFFFu, rmin, 2));
            unsigned enc = fenc(rmin);
            unsigned old = 0xFFFFFFFFu;
            if ((lane & 3) == 0) old = atomicMin(&g_rowmin[row], enc);
            old = __shfl_sync(0xFFFFFFFFu, old, lane & ~3);
            float T = fdec(old < enc ? old : enc) + MARGIN;
#pragma unroll
            for (int nj = 0; nj < 8; nj++)
#pragma unroll
                for (int t = 0; t < 2; t++) {
                    if (sc[nj][t] <= T) {
                        int c = bn + warp_n * 64 + nj * 8 + (lane & 3) * 2 + t;
                        int pos = atomicAdd(&g_cnt[row], 1);
                        if (pos < CAP)
                            g_cand[(size_t)row * CAP + pos] =
                                ((unsigned long long)fenc(sc[nj][t]) << 32) |
                                (unsigned long long)(unsigned)c;
                    }
                }
        }
    }
}

// ---------------------------------------------------------------------------
// Pass 2: filter by converged min, exact re-rank of survivors (bit-identical
// recipe), then codes / STE / loss. One block per row.
// ---------------------------------------------------------------------------
__global__ void finalize_kernel(const float* __restrict__ A,
                                const float* __restrict__ B,
                                float* __restrict__ out_codes,
                                float* __restrict__ out_q) {
    __shared__ unsigned long long sKey;
    const int n = blockIdx.x;
    if (threadIdx.x == 0) sKey = ~0ULL;
    __syncthreads();

    const float zq = g_zsq[n];
    const float thr = fdec(g_rowmin[n]) + FILTER;   // converged min + tight margin
    const float* z = A + (size_t)n * DDIM;
    int cnt = g_cnt[n];
    if (cnt > CAP) cnt = CAP;

    unsigned long long best = ~0ULL;
    for (int i = threadIdx.x; i < cnt; i += blockDim.x) {
        unsigned long long key = g_cand[(size_t)n * CAP + i];
        float sc = fdec((unsigned)(key >> 32));
        if (sc > thr) continue;                     // pruned by converged min
        int c = (int)(key & 0xFFFFFFFFULL);
        const float4* e4 = reinterpret_cast<const float4*>(B + (size_t)c * DDIM);
        const float4* z4 = reinterpret_cast<const float4*>(z);
        float dot = 0.f;
#pragma unroll 4
        for (int k = 0; k < DDIM / 4; k++) {
            float4 ev = __ldg(&e4[k]);
            float4 zv = __ldg(&z4[k]);
            dot = __fmaf_rn(zv.x, ev.x, dot);
            dot = __fmaf_rn(zv.y, ev.y, dot);
            dot = __fmaf_rn(zv.z, ev.z, dot);
            dot = __fmaf_rn(zv.w, ev.w, dot);
        }
        float anchor = __fadd_rn(zq, g_esq[c]);               // fl(z2 + e2)
        float dist = __fsub_rn(anchor, __fadd_rn(dot, dot));  // fl(a - 2*dot)
        unsigned long long k2 =
            ((unsigned long long)__float_as_uint(dist) << 32) |
            (unsigned long long)(unsigned)c;
        best = k2 < best ? k2 : best;
    }
    atomicMin(&sKey, best);
    __syncthreads();

    const int code = (int)(sKey & 0xFFFFFFFFULL);
    if (threadIdx.x == 0) out_codes[n] = (float)code;

    const float* q = B + (size_t)code * DDIM;
    float ls = 0.f;
    for (int i = threadIdx.x; i < DDIM; i += blockDim.x) {
        float qv = q[i];
        float zv = z[i];
        out_q[(size_t)n * DDIM + i] = __fadd_rn(zv, __fsub_rn(qv, zv));
        float d = zv - qv;
        ls = __fmaf_rn(d, d, ls);
    }
#pragma unroll
    for (int o = 16; o > 0; o >>= 1) ls += __shfl_xor_sync(0xFFFFFFFFu, ls, o);
    __shared__ float wsum[8];
    int w = threadIdx.x >> 5;
    if ((threadIdx.x & 31) == 0) wsum[w] = ls;
    __syncthreads();
    if (threadIdx.x == 0) {
        float s = 0.f;
        for (int k = 0; k < (int)(blockDim.x >> 5); k++) s += wsum[k];
        atomicAdd(&g_loss, (double)s);
    }
}

__global__ void loss_kernel(float* __restrict__ out_loss, double inv_nd) {
    if (threadIdx.x == 0) out_loss[0] = (float)(g_loss * inv_nd * 1.25);
}

// ---------------------------------------------------------------------------
extern "C" void kernel_launch(void* const* d_in, const int* in_sizes, int n_in,
                              void* d_out, int out_size) {
    const float* A = (const float*)d_in[0];  // embeddings (4096 x 768)
    const float* B = (const float*)d_in[1];  // codebook  (65536 x 768)
    const int N = in_sizes[0] / DDIM;
    const int K = in_sizes[1] / DDIM;

    float* out = (float*)d_out;
    float* out_codes = out;
    float* out_q = out + N;
    float* out_loss = out + N + (size_t)N * DDIM;

    static const int SMEM_BYTES = 2 * 16384 + 2 * 32768;  // 96 KB
    cudaFuncSetAttribute(pass1_kernel, cudaFuncAttributeMaxDynamicSharedMemorySize,
                         SMEM_BYTES);

    init_kernel<<<(NQ + 255) / 256, 256>>>();

    float* zsq_p; cudaGetSymbolAddress((void**)&zsq_p, g_zsq);
    float* esq_p; cudaGetSymbolAddress((void**)&esq_p, g_esq);
    __half* Ah_p; cudaGetSymbolAddress((void**)&Ah_p, g_Ah);
    __half* Bh_p; cudaGetSymbolAddress((void**)&Bh_p, g_Bh);

    prep_kernel<<<N / PR, 256>>>(A, Ah_p, zsq_p, 1.0f);
    prep_kernel<<<K / PR, 256>>>(B, Bh_p, esq_p, 65536.0f);

    dim3 grid(N / BM, K / BN);   // (32, 256) — m fastest for B-strip L2 reuse
    pass1_kernel<<<grid, 256, SMEM_BYTES>>>();

    finalize_kernel<<<N, 256>>>(A, B, out_codes, out_q);
    loss_kernel<<<1, 32>>>(out_loss, 1.0 / ((double)N * (double)DDIM));
}